// round 6
// baseline (speedup 1.0000x reference)
#include <cuda_runtime.h>

// ---------------- problem constants ----------------
#define NB 4
#define NC 512
#define NG 2048
#define CH 3
#define NP 3
#define NBAS 10
#define OC 64
#define EPSF 1e-6f
#define BNEPS 1e-5f
#define LOG2E_F 1.4426950408889634f
#define PI2F 6.283185307179586f
#define INV2PI_F 0.15915494309189535f
#define PI2_D 6.2831853071795864769
#define SQRT_2_OVER_NBAS 0.4472135954999579f

#define ELEMS (NB * NG * CH * NP)  // 73728

#define NBIN 1024
#define RFACT 15.0f                // window radius = 15 * scale (>13.2 ftz-zero bound)

// sparse k1: one block per (b, c, 32-grid-point tile)
#define K1_BLOCKS (NB * CH * (NG / 32))   // 768

// fused kF+k5 kernel
#define FG 16
#define FBLOCKS (NB * (NG / FG))    // 512
#define FTHREADS 224
#define HALO 4
#define FGH (FG + 2 * HALO)         // 24
#define FCONV (9 * FG)              // 144
#define K5P ((NB * NG) / FBLOCKS)   // 16 positions per block

// output offsets (flattened tuple concat: y_out, n_f, fourier, n_h1, h0_f)
#define OFF_NF  (NB * NG * OC)
#define OFF_FP  (OFF_NF + ELEMS)
#define OFF_NH1 (OFF_FP + ELEMS)
#define OFF_H0  (OFF_NH1 + ELEMS)

// ---------------- scratch (no allocs allowed) ----------------
__device__ float2 g_ctx[NB * CH * NC];   // context (x,y) sorted by x per (b,c)
__device__ float  g_gbx[NB * CH * NG];   // grid x values, binned by value per (b,c)
__device__ int    g_gbi[NB * CH * NG];   // original grid index per binned slot
__device__ float  g_ph0[ELEMS];
__device__ float  g_ph1[ELEMS];
__device__ float  g_conv[ELEMS];
__device__ float  g_psum[9 * FBLOCKS];
__device__ float  g_psq [9 * FBLOCKS];
__device__ unsigned g_bar_arr;           // spin barrier (self-resetting)
__device__ unsigned g_bar_exit;

__device__ __forceinline__ float ex2f(float x) {
    float y;
    asm("ex2.approx.ftz.f32 %0, %1;" : "=f"(y) : "f"(x));
    return y;
}

// ---------------- kernel 0: prep (context sort + grid binning), 24 blocks ----------------
// blocks 0..11: deterministic bitonic sort of (x_c, y_c) per (b,c) -> g_ctx.
// blocks 12..23: value-bin x_g per (b,c) -> g_gbx/g_gbi (order within bin is
// nondeterministic but provably does not affect any output bit: variably-included
// window edge points have exactly-zero ftz weights).
__global__ __launch_bounds__(512) void k0_prep(
    const float* __restrict__ x_c, const float* __restrict__ y_c,
    const float* __restrict__ x_g)
{
    __shared__ float kx[NC];
    __shared__ float ky[NC];
    __shared__ float gx[NG];
    __shared__ int   hist[NBIN];
    __shared__ int   ofs[NBIN];
    __shared__ int   s2[512];

    int unit = blockIdx.x;
    int tid  = threadIdx.x;

    if (unit < 12) {
        int b = unit / 3, c = unit % 3;
        for (int i = tid; i < NC; i += 512) {
            kx[i] = x_c[(b * NC + i) * CH + c];
            ky[i] = y_c[(b * NC + i) * CH + c];
        }
        __syncthreads();
        for (int size = 2; size <= NC; size <<= 1) {
            for (int stride = size >> 1; stride > 0; stride >>= 1) {
                if (tid < NC / 2) {
                    int i = 2 * tid - (tid & (stride - 1));
                    int j = i + stride;
                    bool up = ((i & size) == 0);
                    float xi = kx[i], xj = kx[j];
                    if ((xi > xj) == up) {
                        kx[i] = xj; kx[j] = xi;
                        float t = ky[i]; ky[i] = ky[j]; ky[j] = t;
                    }
                }
                __syncthreads();
            }
        }
        for (int i = tid; i < NC; i += 512)
            g_ctx[(b * CH + c) * NC + i] = make_float2(kx[i], ky[i]);
    } else {
        int u = unit - 12;
        int b = u / 3, c = u % 3;
        for (int i = tid; i < NG; i += 512)
            gx[i] = x_g[(b * NG + i) * CH + c];
        for (int i = tid; i < NBIN; i += 512) hist[i] = 0;
        __syncthreads();
        for (int i = tid; i < NG; i += 512) {
            int bin = (int)((gx[i] + 5.0f) * (NBIN / 10.0f));
            bin = min(max(bin, 0), NBIN - 1);
            atomicAdd(&hist[bin], 1);
        }
        __syncthreads();
        // exclusive scan of 1024 bins: pair-sum then Hillis-Steele over 512
        int a0 = hist[2 * tid], a1 = hist[2 * tid + 1];
        s2[tid] = a0 + a1;
        __syncthreads();
        for (int d = 1; d < 512; d <<= 1) {
            int v = s2[tid];
            int w = (tid >= d) ? s2[tid - d] : 0;
            __syncthreads();
            s2[tid] = v + w;
            __syncthreads();
        }
        int excl = (tid > 0) ? s2[tid - 1] : 0;
        ofs[2 * tid]     = excl;
        ofs[2 * tid + 1] = excl + a0;
        (void)a1;
        __syncthreads();
        for (int i = tid; i < NG; i += 512) {
            float v = gx[i];
            int bin = (int)((v + 5.0f) * (NBIN / 10.0f));
            bin = min(max(bin, 0), NBIN - 1);
            int p = atomicAdd(&ofs[bin], 1);
            g_gbx[(b * CH + c) * NG + p] = v;
            g_gbi[(b * CH + c) * NG + p] = i;
        }
    }
}

// ---------------- kernel 1: windowed RBF sums ----------------
// 768 blocks x 256 threads. Block = (b, c, tile of 32 value-adjacent grid pts).
// Each of 8 warps covers fixed context chunks {w, w+8, w+16, w+24} (16 pts each),
// intersected with the warp's per-p window [lo - 15*s_p, hi + 15*s_p].
// Fixed chunk boundaries + ascending combine order => bit-deterministic sums.
__global__ __launch_bounds__(256) void k1_rbf(const float* __restrict__ sigma)
{
    __shared__ float2 sctx[NC];            // 4KB sorted context
    __shared__ float  sxv[32];
    __shared__ int    sgi[32];
    __shared__ float  sacc[8 * 6 * 32];    // [warp][j][lane]

    int unit = blockIdx.x;
    int gt = unit % (NG / 32);
    int c  = (unit / (NG / 32)) % CH;
    int b  = unit / ((NG / 32) * CH);
    int tid = threadIdx.x;
    int lane = tid & 31, w = tid >> 5;

    const float2* ctx = g_ctx + (b * CH + c) * NC;
    for (int i = tid; i < NC; i += 256) sctx[i] = ctx[i];
    if (tid < 32) {
        sxv[tid] = g_gbx[(b * CH + c) * NG + gt * 32 + tid];
        sgi[tid] = g_gbi[(b * CH + c) * NG + gt * 32 + tid];
    }
    __syncthreads();

    float xg = sxv[lane];

    // warp value range
    float lo = xg, hi = xg;
#pragma unroll
    for (int st = 16; st; st >>= 1) {
        lo = fminf(lo, __shfl_xor_sync(0xffffffffu, lo, st));
        hi = fmaxf(hi, __shfl_xor_sync(0xffffffffu, hi, st));
    }

    float ks[3], rr[3];
#pragma unroll
    for (int p = 0; p < 3; p++) {
        float s = expf(sigma[p]) + EPSF;
        ks[p] = -0.5f * LOG2E_F / (s * s);
        rr[p] = RFACT * s;
    }

    float h0[3], h1[3];
#pragma unroll
    for (int p = 0; p < 3; p++) {
        float vlo = lo - rr[p], vhi = hi + rr[p];
        int i0, i1;
        { int l = 0, h = NC; while (l < h) { int m = (l + h) >> 1; if (sctx[m].x < vlo) l = m + 1; else h = m; } i0 = l; }
        { int l = 0, h = NC; while (l < h) { int m = (l + h) >> 1; if (sctx[m].x < vhi) l = m + 1; else h = m; } i1 = l; }
        float kp = ks[p];
        float a0 = 0.f, a1 = 0.f;
#pragma unroll
        for (int cc = 0; cc < 4; cc++) {
            int ci = w + cc * 8;                 // chunk 0..31 (16 pts each)
            int a  = max(i0, ci * 16);
            int bb = min(i1, ci * 16 + 16);
#pragma unroll 2
            for (int i = a; i < bb; i++) {
                float2 cy = sctx[i];
                float d = xg - cy.x;
                float wv = ex2f(d * d * kp);
                a0 += wv;
                a1 = fmaf(wv, cy.y, a1);
            }
        }
        h0[p] = a0; h1[p] = a1;
    }

#pragma unroll
    for (int p = 0; p < 3; p++) {
        sacc[(w * 6 + p * 2 + 0) * 32 + lane] = h0[p];
        sacc[(w * 6 + p * 2 + 1) * 32 + lane] = h1[p];
    }
    __syncthreads();

    if (tid < 192) {
        int j = tid >> 5;      // 0..5
        int l = tid & 31;
        float v = 0.f;
#pragma unroll
        for (int s = 0; s < 8; s++) v += sacc[(s * 6 + j) * 32 + l];
        int p = j >> 1;
        int base = ((b * NG + sgi[l]) * CH + c) * NP + p;
        if ((j & 1) == 0) g_ph0[base] = v;
        else              g_ph1[base] = v;
    }
}

// fp32 Cody-Waite cos reduction (no FP64), abs err ~7e-7
__device__ __forceinline__ float cos_red(float arg) {
    const float F2PI     = (float)PI2_D;
    const float F2PI_RES = (float)(PI2_D - (double)((float)PI2_D));
    float n = rintf(arg * INV2PI_F);
    float r = fmaf(-n, F2PI, arg);
    r = fmaf(-n, F2PI_RES, r);
    return __cosf(r);
}

// ---------------- kernel F5: combine + Fourier + conv + BN + final linear ----------------
// 512 blocks x 224 threads; global spin barrier between conv-stats and BN/GEMM.
__global__ __launch_bounds__(FTHREADS, 4) void kF5(
    const float* __restrict__ x_g, const float* __restrict__ sigma,
    const float* __restrict__ mu,  const float* __restrict__ eps1,
    const float* __restrict__ b_u, const float* __restrict__ rw,
    const float* __restrict__ w1, const float* __restrict__ b1,
    const float* __restrict__ w2, const float* __restrict__ b2,
    const float* __restrict__ w3, const float* __restrict__ b3,
    const float* __restrict__ gamma, const float* __restrict__ beta,
    const float* __restrict__ gw,    const float* __restrict__ gb,
    float* __restrict__ out)
{
    __shared__ float spos[FGH * 9];
    __shared__ float ssw[NBAS * 3];
    __shared__ float ssb[NBAS * 3];
    __shared__ float srw[NBAS];
    __shared__ float sgw[OC * 19];
    __shared__ float sgb2[OC];
    __shared__ float sA[9], sB[9];
    __shared__ float feat[K5P * 18];

    int tid = threadIdx.x;
    int b   = blockIdx.x / (NG / FG);
    int gt  = blockIdx.x % (NG / FG);
    int g0  = gt * FG;

    if (tid < NBAS * 3) {
        int k = tid / 3, p = tid % 3;
        float wmu  = expf(mu[p]);
        float wstd = 1.0f / (expf(sigma[p]) + EPSF);
        float e = eps1[(b * NBAS + k) * NP + p];
        float u = b_u [(b * NBAS + k) * NP + p];
        ssw[tid] = __fadd_rn(wmu, __fmul_rn(wstd, e));
        ssb[tid] = __fmul_rn(PI2F, u);
    }
    if (tid < NBAS) srw[tid] = rw[tid];
    __syncthreads();

    // Phase 1: pos = n_h1 + fourier
    if (tid < FGH * 9) {
        int jj = tid / 9;
        int cp = tid % 9;
        int c = cp / 3, p = cp % 3;
        int g = g0 - HALO + jj;
        float pos = 0.f;
        if (g >= 0 && g < NG) {
            int idx = ((b * NG + g) * CH + c) * NP + p;
            float h0 = g_ph0[idx];
            float h1 = g_ph1[idx];
            float nh1 = h1 / (h0 + EPSF);

            float xg = x_g[(b * NG + g) * CH + c];
            float acc = 0.f;
#pragma unroll
            for (int k = 0; k < NBAS; k++) {
                float arg = __fadd_rn(__fmul_rn(ssw[k * 3 + p], xg), ssb[k * 3 + p]);
                acc = __fadd_rn(acc, __fmul_rn(srw[k], cos_red(arg)));
            }
            float fp = SQRT_2_OVER_NBAS * acc;
            pos = nh1 + fp;

            if (jj >= HALO && jj < HALO + FG) {
                out[OFF_NH1 + idx] = nh1;
                out[OFF_FP  + idx] = fp;
                out[OFF_H0  + idx] = h0;
            }
        }
        spos[tid] = pos;
    }
    __syncthreads();

    // Phase 2: depthwise conv + per-cp partial stats
    float acc = 0.f, sq = 0.f;
    if (tid < FCONV) {
        int cp = tid >> 4;
        int j  = tid & 15;
        int c = cp / 3, p = cp % 3;
        int g = g0 + j;

        const float* w; const float* bias; int ksz, pad;
        if (p == 0)      { w = w1; bias = b1; ksz = 3; pad = 1; }
        else if (p == 1) { w = w2; bias = b2; ksz = 5; pad = 2; }
        else             { w = w3; bias = b3; ksz = 9; pad = 4; }

        acc = bias[c];
        int jj0 = j - pad + HALO;
        for (int t = 0; t < ksz; t++)
            acc = fmaf(w[c * ksz + t], spos[(jj0 + t) * 9 + cp], acc);

        g_conv[((b * NG + g) * CH + c) * NP + p] = acc;
        sq = acc * acc;
    }
#pragma unroll
    for (int st = 8; st > 0; st >>= 1) {
        acc += __shfl_down_sync(0xffffffffu, acc, st, 16);
        sq  += __shfl_down_sync(0xffffffffu, sq,  st, 16);
    }
    if (tid < FCONV && (tid & 15) == 0) {
        int cp = tid >> 4;
        g_psum[cp * FBLOCKS + blockIdx.x] = acc;
        g_psq [cp * FBLOCKS + blockIdx.x] = sq;
    }

    // ---- global spin barrier (all 512 blocks co-resident) ----
    __threadfence();
    __syncthreads();
    if (tid == 0) {
        atomicAdd(&g_bar_arr, 1u);
        while (atomicAdd(&g_bar_arr, 0u) < (unsigned)FBLOCKS) __nanosleep(64);
    }
    __syncthreads();
    __threadfence();

    // ---- Phase 3: BN finalize + feat + 18->64 linear for K5P positions ----
    int pos0 = blockIdx.x * K5P;

    for (int t = tid; t < OC * 18; t += FTHREADS)
        sgw[(t / 18) * 19 + (t % 18)] = gw[t];
    if (tid < OC) sgb2[tid] = gb[tid];

    {
        float s = 0.f, q = 0.f;
        int cp = tid >> 4, l = tid & 15;
        if (tid < 144) {
            for (int k = l; k < FBLOCKS; k += 16) {
                s += g_psum[cp * FBLOCKS + k];
                q += g_psq [cp * FBLOCKS + k];
            }
        }
#pragma unroll
        for (int st = 8; st > 0; st >>= 1) {
            s += __shfl_down_sync(0xffffffffu, s, st, 16);
            q += __shfl_down_sync(0xffffffffu, q, st, 16);
        }
        if (tid < 144 && l == 0) {
            const float invn = 1.0f / (float)(NB * NG);
            float m   = s * invn;
            float var = q * invn - m * m;
            float rs  = rsqrtf(var + BNEPS);
            int c = cp / 3, p = cp % 3;
            float ga = gamma[p * CH + c];
            float be = beta [p * CH + c];
            sA[cp] = rs * ga;
            sB[cp] = be - m * rs * ga;
        }
    }
    __syncthreads();

    for (int t = tid; t < K5P * 18; t += FTHREADS) {
        int pl = t / 18, k = t % 18;
        int pos = pos0 + pl;
        float v;
        if (k < 9) {
            v = out[OFF_H0 + pos * 9 + k];
        } else {
            int cp = k - 9;
            v = fmaf(g_conv[pos * 9 + cp], sA[cp], sB[cp]);
            out[OFF_NF + pos * 9 + cp] = v;
        }
        feat[pl * 18 + k] = v;
    }
    __syncthreads();

    for (int t = tid; t < K5P * OC; t += FTHREADS) {
        int pl = t / OC, oc = t % OC;
        float a2 = sgb2[oc];
#pragma unroll
        for (int f = 0; f < 18; f++)
            a2 = fmaf(feat[pl * 18 + f], sgw[oc * 19 + f], a2);
        out[(pos0 + pl) * OC + oc] = a2;
    }

    // ---- self-reset for next graph replay ----
    if (tid == 0) {
        unsigned e = atomicAdd(&g_bar_exit, 1u);
        if (e == (unsigned)(FBLOCKS - 1)) {
            g_bar_arr = 0u;
            g_bar_exit = 0u;
            __threadfence();
        }
    }
}

// ---------------- launch ----------------
extern "C" void kernel_launch(void* const* d_in, const int* in_sizes, int n_in,
                              void* d_out, int out_size)
{
    const float* x_c   = (const float*)d_in[0];
    const float* y_c   = (const float*)d_in[1];
    const float* x_g   = (const float*)d_in[2];
    const float* sigma = (const float*)d_in[3];
    const float* mu    = (const float*)d_in[4];
    const float* eps1  = (const float*)d_in[5];
    const float* b_u   = (const float*)d_in[6];
    const float* rw    = (const float*)d_in[7];
    const float* w1    = (const float*)d_in[8];
    const float* b1    = (const float*)d_in[9];
    const float* w2    = (const float*)d_in[10];
    const float* b2    = (const float*)d_in[11];
    const float* w3    = (const float*)d_in[12];
    const float* b3    = (const float*)d_in[13];
    const float* gam   = (const float*)d_in[14];
    const float* bet   = (const float*)d_in[15];
    const float* gw    = (const float*)d_in[16];
    const float* gb    = (const float*)d_in[17];
    float* out = (float*)d_out;

    k0_prep<<<24, 512>>>(x_c, y_c, x_g);
    k1_rbf<<<K1_BLOCKS, 256>>>(sigma);
    kF5<<<FBLOCKS, FTHREADS>>>(x_g, sigma, mu, eps1, b_u, rw,
                               w1, b1, w2, b2, w3, b3,
                               gam, bet, gw, gb, out);
}